// round 1
// baseline (speedup 1.0000x reference)
#include <cuda_runtime.h>
#include <math.h>

#define BSZ    65536
#define TT     31
#define HIDN   128
#define NVOCAB 19
#define NCONST 40
#define INSZ   133
#define RPB    64
#define NTH    512

#define OUT_CV  2031616   // BSZ*TT
#define OUT_LP  4063232   // 2*BSZ*TT
#define OUT_TOT 4194304

// shared layout (float indices)
#define S_WHH  0            // [k][j] 128x128
#define S_HEAD 16384        // [k][64] interleaved float2: (row l, row l+32)
#define S_IHT  24576        // [c][j] 124x128
#define S_H    40448        // [row][128]
#define S_ACC  48640        // [row][128]
#define S_BH   56832        // 64 head biases
#define S_LP   56896        // 64 per-row logprob accumulators
#define S_NF   56960
// int region
#define SI_POS 0
#define SI_SP  64
#define SI_ACT 128
#define SI_STK 192          // 64 rows x 8
#define SI_N   704
#define SMEM_BYTES ((S_NF + SI_N) * 4)

#define FULLM 0xffffffffu

__device__ __forceinline__ float gumbelf(float u) {
    float inner = -logf(u + 1e-9f);
    return -logf(inner + 1e-9f);
}
__device__ __forceinline__ float wmaxf(float v) {
#pragma unroll
    for (int o = 16; o; o >>= 1) v = fmaxf(v, __shfl_xor_sync(FULLM, v, o));
    return v;
}
__device__ __forceinline__ float wsumf(float v) {
#pragma unroll
    for (int o = 16; o; o >>= 1) v += __shfl_xor_sync(FULLM, v, o);
    return v;
}
// argmax with first-index tie-break (matches jnp.argmax); carries logp of winner
__device__ __forceinline__ void wargmax(float& s, int& i, float& lp) {
#pragma unroll
    for (int o = 16; o; o >>= 1) {
        float s2 = __shfl_xor_sync(FULLM, s, o);
        int   i2 = __shfl_xor_sync(FULLM, i, o);
        float l2 = __shfl_xor_sync(FULLM, lp, o);
        if (s2 > s || (s2 == s && i2 < i)) { s = s2; i = i2; lp = l2; }
    }
}

template<int CNT>
__device__ void step_group(float* sm, int* si,
                           const float* __restrict__ noise_tok,
                           const float* __restrict__ noise_c,
                           float* __restrict__ out,
                           int t, int gbase, const int* grp, int lane)
{
    // prefetch gumbel noise (indices independent of this step's choice)
    float u_t[CNT], u_a[CNT], u_b[CNT];
#pragma unroll
    for (int i = 0; i < CNT; i++) {
        long long bt = (long long)t * BSZ + (gbase + grp[i]);
        u_t[i] = (lane < NVOCAB) ? __ldg(&noise_tok[bt * NVOCAB + lane]) : 0.f;
        u_a[i] = (lane >= NVOCAB) ? __ldg(&noise_c[bt * NCONST + (lane - NVOCAB)]) : 0.f;
        u_b[i] = (lane < 27) ? __ldg(&noise_c[bt * NCONST + (lane + 13)]) : 0.f;
    }

    // Phase A: z = W_hh * h  (lane owns outputs 4l..4l+3; amortize W across CNT rows)
    float4 z[CNT];
#pragma unroll
    for (int i = 0; i < CNT; i++) z[i] = make_float4(0.f, 0.f, 0.f, 0.f);
    const float4* whh = (const float4*)(sm + S_WHH);
#pragma unroll 4
    for (int k = 0; k < HIDN; k++) {
        float4 wv = whh[k * 32 + lane];
#pragma unroll
        for (int i = 0; i < CNT; i++) {
            float hk = sm[S_H + grp[i] * HIDN + k];
            z[i].x = fmaf(hk, wv.x, z[i].x);
            z[i].y = fmaf(hk, wv.y, z[i].y);
            z[i].z = fmaf(hk, wv.z, z[i].z);
            z[i].w = fmaf(hk, wv.w, z[i].w);
        }
    }
#pragma unroll
    for (int i = 0; i < CNT; i++) {
        float4 a = *(const float4*)(sm + S_ACC + grp[i] * HIDN + 4 * lane);
        float4 h;
        h.x = tanhf(z[i].x + a.x);
        h.y = tanhf(z[i].y + a.y);
        h.z = tanhf(z[i].z + a.z);
        h.w = tanhf(z[i].w + a.w);
        *(float4*)(sm + S_H + grp[i] * HIDN + 4 * lane) = h;
    }
    __syncwarp();

    // Phase B: head logits (lane owns head rows l and l+32; 0-18 tok, 19-58 const)
    float2 ho[CNT];
#pragma unroll
    for (int i = 0; i < CNT; i++) ho[i] = make_float2(0.f, 0.f);
    const float2* whd = (const float2*)(sm + S_HEAD);
#pragma unroll 4
    for (int k = 0; k < HIDN; k++) {
        float2 wv = whd[k * 32 + lane];
#pragma unroll
        for (int i = 0; i < CNT; i++) {
            float hk = sm[S_H + grp[i] * HIDN + k];
            ho[i].x = fmaf(hk, wv.x, ho[i].x);
            ho[i].y = fmaf(hk, wv.y, ho[i].y);
        }
    }
    float blo = sm[S_BH + lane];
    float bhi = sm[S_BH + 32 + lane];
    const float NEGINF = -INFINITY;

    // Phase C: per-row sampling + tree bookkeeping
#pragma unroll
    for (int i = 0; i < CNT; i++) {
        int row = grp[i];
        int gr  = gbase + row;
        int p   = si[SI_POS + row];

        // token head: log_softmax with depth mask, then argmax(logp + g)
        float ltok = NEGINF;
        if (lane < NVOCAB) {
            ltok = ho[i].x + blo;
            if (p >= 15 && lane < 6) ltok = NEGINF;   // deepest layer: leaves only
        }
        float m   = wmaxf(ltok);
        float e   = (lane < NVOCAB) ? expf(ltok - m) : 0.f;
        float lse = logf(wsumf(e));
        float lpt = ltok - m - lse;
        float sc  = lpt + gumbelf(u_t[i]);
        int ci = lane; float lpw = lpt;
        wargmax(sc, ci, lpw);
        int choice = ci; float lp_tok = lpw;

        // constant head (40 logits spread over two slots/lane)
        float la = (lane >= NVOCAB) ? (ho[i].x + blo) : NEGINF;   // c idx lane-19 (0..12)
        float lb = (lane < 27)      ? (ho[i].y + bhi) : NEGINF;   // c idx lane+13 (13..39)
        float mc   = wmaxf(fmaxf(la, lb));
        float ec   = ((lane >= NVOCAB) ? expf(la - mc) : 0.f)
                   + ((lane < 27)      ? expf(lb - mc) : 0.f);
        float lsec = logf(wsumf(ec));
        float lpa = la - mc - lsec;
        float lpb = lb - mc - lsec;
        float sa = lpa + gumbelf(u_a[i]);
        float sb = lpb + gumbelf(u_b[i]);
        int iaa = lane - NVOCAB;
        int ibb = lane + 13;
        float s_l, lp_l; int i_l;
        if (sb > sa || (sb == sa && ibb < iaa)) { s_l = sb; i_l = ibb; lp_l = lpb; }
        else                                    { s_l = sa; i_l = iaa; lp_l = lpa; }
        wargmax(s_l, i_l, lp_l);
        int cchoice = i_l; float lp_c = lp_l;

        bool is_const = (choice == 18);
        if (lane == 0) {
            sm[S_LP + row] += lp_tok + (is_const ? lp_c : 0.f);
            out[gr * TT + p] = (float)choice;
            if (is_const) out[OUT_CV + gr * TT + p] = -10.f + 0.5f * (float)cchoice;
            int arity = (choice < 4) ? 2 : ((choice < 6) ? 1 : 0);
            int sp = si[SI_SP + row];
            if (arity == 2) {
                int wsp = sp < 7 ? sp : 7;
                si[SI_STK + row * 8 + wsp] = 2 * p + 2;
            }
            int sp1 = sp + (arity == 2 ? 1 : 0);
            int nxt, sp2;
            if (arity != 0) { nxt = 2 * p + 1; sp2 = sp1; }
            else {
                int ridx = sp1 - 1; if (ridx < 0) ridx = 0; if (ridx > 7) ridx = 7;
                nxt = (sp1 > 0) ? si[SI_STK + row * 8 + ridx] : -1;
                sp2 = (sp1 > 0) ? sp1 - 1 : 0;
            }
            if (nxt > TT - 1) nxt = -1;
            si[SI_POS + row] = nxt;
            si[SI_SP + row]  = sp2;
            si[SI_ACT + row] = (nxt >= 0) ? 1 : 0;
        }
        // fold chosen token's 4-bit code into the W_ih accumulator (position unique -> add)
        if (choice & 15) {
            int j0 = 4 * lane;
            float4 a = *(const float4*)(sm + S_ACC + row * HIDN + j0);
            int cb = 4 * p;
#pragma unroll
            for (int b = 0; b < 4; b++) {
                if (choice & (1 << b)) {
                    const float4 wv = *(const float4*)(sm + S_IHT + (cb + b) * HIDN + j0);
                    a.x += wv.x; a.y += wv.y; a.z += wv.z; a.w += wv.w;
                }
            }
            *(float4*)(sm + S_ACC + row * HIDN + j0) = a;
        }
    }
}

__global__ void __launch_bounds__(NTH, 1)
rnn_main(const float* __restrict__ x,
         const float* __restrict__ noise_tok,
         const float* __restrict__ noise_c,
         const float* __restrict__ W_ih,
         const float* __restrict__ W_hh,
         const float* __restrict__ b_ih,
         const float* __restrict__ b_hh,
         const float* __restrict__ W_out,
         const float* __restrict__ b_out,
         const float* __restrict__ W_c,
         const float* __restrict__ b_c,
         float* __restrict__ out)
{
    extern __shared__ float sm[];
    int* si = (int*)(sm + S_NF);
    int tid = threadIdx.x;
    int gbase = blockIdx.x * RPB;

    // stage W_hh transposed
    for (int idx = tid; idx < HIDN * HIDN; idx += NTH) {
        int j = idx / HIDN, k = idx % HIDN;
        sm[S_WHH + k * HIDN + j] = W_hh[idx];
    }
    // zero head region (padding rows 59-63 must be finite)
    for (int idx = tid; idx < HIDN * 64; idx += NTH) sm[S_HEAD + idx] = 0.f;
    __syncthreads();
    // stage head weights interleaved: [k][2*l + s] = W_head[l + 32*s][k]
    for (int idx = tid; idx < NVOCAB * HIDN; idx += NTH) {
        int r = idx / HIDN, k = idx % HIDN;
        sm[S_HEAD + k * 64 + 2 * (r & 31) + (r >> 5)] = W_out[idx];
    }
    for (int idx = tid; idx < NCONST * HIDN; idx += NTH) {
        int rc = idx / HIDN, k = idx % HIDN;
        int r = rc + NVOCAB;
        sm[S_HEAD + k * 64 + 2 * (r & 31) + (r >> 5)] = W_c[idx];
    }
    // stage W_ih columns 0..123 transposed
    for (int idx = tid; idx < 124 * HIDN; idx += NTH) {
        int j = idx / 124, c = idx % 124;
        sm[S_IHT + c * HIDN + j] = W_ih[j * INSZ + c];
    }
    if (tid < 64) {
        float v = 0.f;
        if (tid < NVOCAB) v = b_out[tid];
        else if (tid < NVOCAB + NCONST) v = b_c[tid - NVOCAB];
        sm[S_BH + tid] = v;
    }

    // per-row init: acc = b_ih + b_hh + x @ W_ih[:,124:133].T ; h = 0
    int w = tid >> 5, lane = tid & 31;
    int w4 = w * 4;
#pragma unroll
    for (int q = 0; q < 4; q++) {
        int row = w4 + q;
        int gr = gbase + row;
        int j0 = 4 * lane;
        float4 a;
        a.x = b_ih[j0 + 0] + b_hh[j0 + 0];
        a.y = b_ih[j0 + 1] + b_hh[j0 + 1];
        a.z = b_ih[j0 + 2] + b_hh[j0 + 2];
        a.w = b_ih[j0 + 3] + b_hh[j0 + 3];
        for (int f = 0; f < 9; f++) {
            float xv = x[gr * 9 + f];
            int c = 124 + f;
            a.x = fmaf(xv, W_ih[(j0 + 0) * INSZ + c], a.x);
            a.y = fmaf(xv, W_ih[(j0 + 1) * INSZ + c], a.y);
            a.z = fmaf(xv, W_ih[(j0 + 2) * INSZ + c], a.z);
            a.w = fmaf(xv, W_ih[(j0 + 3) * INSZ + c], a.w);
        }
        *(float4*)(sm + S_ACC + row * HIDN + j0) = a;
        *(float4*)(sm + S_H + row * HIDN + j0) = make_float4(0.f, 0.f, 0.f, 0.f);
    }
    if (lane < 4) {
        si[SI_POS + w4 + lane] = 0;
        si[SI_SP + w4 + lane] = 0;
        si[SI_ACT + w4 + lane] = 1;
        sm[S_LP + w4 + lane] = 0.f;
    }
    __syncthreads();

    // main decode loop: warps run fully independently (own rows only)
    for (int t = 0; t < TT; t++) {
        int actm = 0;
#pragma unroll
        for (int q = 0; q < 4; q++) if (si[SI_ACT + w4 + q]) actm |= (1 << q);
        int cnt = __popc(actm);
        if (cnt == 0) break;
        int grp[4];
        int mrem = actm;
#pragma unroll
        for (int q = 0; q < 4; q++) {
            int b = __ffs(mrem) - 1;
            grp[q] = w4 + (b >= 0 ? b : 0);
            mrem &= (mrem - 1);
        }
        switch (cnt) {
            case 4: step_group<4>(sm, si, noise_tok, noise_c, out, t, gbase, grp, lane); break;
            case 3: step_group<3>(sm, si, noise_tok, noise_c, out, t, gbase, grp, lane); break;
            case 2: step_group<2>(sm, si, noise_tok, noise_c, out, t, gbase, grp, lane); break;
            default: step_group<1>(sm, si, noise_tok, noise_c, out, t, gbase, grp, lane); break;
        }
        __syncwarp();
    }

    if (lane < 4) {
        out[OUT_LP + gbase + w4 + lane] = sm[S_LP + w4 + lane];
    }
}

__global__ void init_out_kernel(float* __restrict__ out)
{
    float4* o4 = (float4*)out;
    const int n4 = OUT_TOT / 4;
    int stride = gridDim.x * blockDim.x;
    for (int i = blockIdx.x * blockDim.x + threadIdx.x; i < n4; i += stride) {
        float v = (i * 4 < OUT_CV) ? -1.f : 0.f;   // OUT_CV divisible by 4
        o4[i] = make_float4(v, v, v, v);
    }
}

extern "C" void kernel_launch(void* const* d_in, const int* in_sizes, int n_in,
                              void* d_out, int out_size)
{
    const float* x    = (const float*)d_in[0];
    const float* nt   = (const float*)d_in[1];
    const float* nc   = (const float*)d_in[2];
    const float* wih  = (const float*)d_in[3];
    const float* whh  = (const float*)d_in[4];
    const float* bih  = (const float*)d_in[5];
    const float* bhh  = (const float*)d_in[6];
    const float* wout = (const float*)d_in[7];
    const float* bout = (const float*)d_in[8];
    const float* wc   = (const float*)d_in[9];
    const float* bc   = (const float*)d_in[10];
    float* out = (float*)d_out;

    cudaFuncSetAttribute((const void*)rnn_main,
                         cudaFuncAttributeMaxDynamicSharedMemorySize, SMEM_BYTES);
    init_out_kernel<<<512, 256>>>(out);
    rnn_main<<<BSZ / RPB, NTH, SMEM_BYTES>>>(x, nt, nc, wih, whh, bih, bhh,
                                             wout, bout, wc, bc, out);
}

// round 2
// speedup vs baseline: 1.1797x; 1.1797x over previous
#include <cuda_runtime.h>
#include <math.h>

#define BSZ    65536
#define TT     31
#define HIDN   128
#define NVOCAB 19
#define NCONST 40
#define INSZ   133
#define RPB    64
#define NTH    512

#define OUT_CV  2031616   // BSZ*TT
#define OUT_LP  4063232   // 2*BSZ*TT
#define OUT_TOT 4194304

// shared float layout
#define S_WHH  0                 // [k][128] W_hh transposed
#define S_TOK  16384             // [k][32]  token head (19 real)
#define S_CON  20480             // [k][64]  const head (40 real)
#define S_H    28672             // [64][128]
#define S_ACC  36864             // [64][128]
#define S_BTOK 45056             // 32
#define S_BCON 45088             // 64
#define S_LP   45152             // 64
#define S_NF   45216
// int region
#define SI_POS  0
#define SI_SP   64
#define SI_ACTF 128
#define SI_STK  192              // 64 x 8
#define SI_LIST 704              // 64
#define SI_CNT  768
#define SI_N    772
#define SMEM_BYTES ((S_NF + SI_N) * 4)

#define FULLM 0xffffffffu

__device__ float g_WihT[INSZ * HIDN];   // [c][j]

__device__ __forceinline__ float gumbelf(float u) {
    float inner = -logf(u + 1e-9f);
    return -logf(inner + 1e-9f);
}
__device__ __forceinline__ float wmaxf(float v) {
#pragma unroll
    for (int o = 16; o; o >>= 1) v = fmaxf(v, __shfl_xor_sync(FULLM, v, o));
    return v;
}
__device__ __forceinline__ float wsumf(float v) {
#pragma unroll
    for (int o = 16; o; o >>= 1) v += __shfl_xor_sync(FULLM, v, o);
    return v;
}
__device__ __forceinline__ void wargmax(float& s, int& i, float& lp) {
#pragma unroll
    for (int o = 16; o; o >>= 1) {
        float s2 = __shfl_xor_sync(FULLM, s, o);
        int   i2 = __shfl_xor_sync(FULLM, i, o);
        float l2 = __shfl_xor_sync(FULLM, lp, o);
        if (s2 > s || (s2 == s && i2 < i)) { s = s2; i = i2; lp = l2; }
    }
}

template<int CNT>
__device__ __forceinline__ void step_group(float* sm, int* si,
                           const float* __restrict__ noise_tok,
                           const float* __restrict__ noise_c,
                           float* __restrict__ out,
                           int t, int gbase, const int* grp, int lane)
{
    float u_t[CNT];
    int p[CNT];
#pragma unroll
    for (int i = 0; i < CNT; i++) {
        int row = grp[i];
        long long bt = (long long)t * BSZ + (gbase + row);
        u_t[i] = (lane < NVOCAB) ? __ldg(&noise_tok[bt * NVOCAB + lane]) : 0.f;
        p[i] = si[SI_POS + row];
    }

    // Phase A: z = W_hh^T-staged GEMV; lane owns outputs 4l..4l+3
    float4 z[CNT];
#pragma unroll
    for (int i = 0; i < CNT; i++) z[i] = make_float4(0.f, 0.f, 0.f, 0.f);
    const float4* whh = (const float4*)(sm + S_WHH);
#pragma unroll 8
    for (int k4 = 0; k4 < 32; k4++) {
        float4 hv[CNT];
#pragma unroll
        for (int i = 0; i < CNT; i++)
            hv[i] = *(const float4*)(sm + S_H + grp[i] * HIDN + 4 * k4);
#pragma unroll
        for (int b = 0; b < 4; b++) {
            float4 wv = whh[(4 * k4 + b) * 32 + lane];
#pragma unroll
            for (int i = 0; i < CNT; i++) {
                float hk = (b == 0) ? hv[i].x : (b == 1) ? hv[i].y : (b == 2) ? hv[i].z : hv[i].w;
                z[i].x = fmaf(hk, wv.x, z[i].x);
                z[i].y = fmaf(hk, wv.y, z[i].y);
                z[i].z = fmaf(hk, wv.z, z[i].z);
                z[i].w = fmaf(hk, wv.w, z[i].w);
            }
        }
    }
#pragma unroll
    for (int i = 0; i < CNT; i++) {
        float4 a = *(const float4*)(sm + S_ACC + grp[i] * HIDN + 4 * lane);
        float4 h;
        h.x = tanhf(z[i].x + a.x);
        h.y = tanhf(z[i].y + a.y);
        h.z = tanhf(z[i].z + a.z);
        h.w = tanhf(z[i].w + a.w);
        *(float4*)(sm + S_H + grp[i] * HIDN + 4 * lane) = h;
    }
    __syncwarp();

    // Phase B: token head logits (lane = vocab index)
    float tk[CNT];
#pragma unroll
    for (int i = 0; i < CNT; i++) tk[i] = 0.f;
#pragma unroll 8
    for (int k4 = 0; k4 < 32; k4++) {
        float4 hv[CNT];
#pragma unroll
        for (int i = 0; i < CNT; i++)
            hv[i] = *(const float4*)(sm + S_H + grp[i] * HIDN + 4 * k4);
#pragma unroll
        for (int b = 0; b < 4; b++) {
            float wv = sm[S_TOK + (4 * k4 + b) * 32 + lane];
#pragma unroll
            for (int i = 0; i < CNT; i++) {
                float hk = (b == 0) ? hv[i].x : (b == 1) ? hv[i].y : (b == 2) ? hv[i].z : hv[i].w;
                tk[i] = fmaf(hk, wv, tk[i]);
            }
        }
    }
    float btok = sm[S_BTOK + lane];
    const float NEGINF = -INFINITY;

    // Phase C: per-row sampling + tree bookkeeping
#pragma unroll
    for (int i = 0; i < CNT; i++) {
        int row = grp[i];
        int gr  = gbase + row;
        int pi  = p[i];

        float ltok = NEGINF;
        if (lane < NVOCAB) {
            ltok = tk[i] + btok;
            if (pi >= 15 && lane < 6) ltok = NEGINF;
        }
        float m   = wmaxf(ltok);
        float e   = (lane < NVOCAB) ? expf(ltok - m) : 0.f;
        float lse = logf(wsumf(e));
        float lpt = ltok - m - lse;
        float sc  = lpt + gumbelf(u_t[i]);
        int ci = lane; float lpw = lpt;
        wargmax(sc, ci, lpw);
        int choice = ci; float lp_tok = lpw;

        bool is_const = (choice == 18);
        float lp_c = 0.f; int cchoice = 0;
        if (is_const) {   // warp-uniform branch (choice uniform after argmax)
            float2 co = make_float2(0.f, 0.f);
#pragma unroll 8
            for (int k4 = 0; k4 < 32; k4++) {
                float4 hv = *(const float4*)(sm + S_H + row * HIDN + 4 * k4);
#pragma unroll
                for (int b = 0; b < 4; b++) {
                    float2 wc = *(const float2*)(sm + S_CON + (4 * k4 + b) * 64 + 2 * lane);
                    float hk = (b == 0) ? hv.x : (b == 1) ? hv.y : (b == 2) ? hv.z : hv.w;
                    co.x = fmaf(hk, wc.x, co.x);
                    co.y = fmaf(hk, wc.y, co.y);
                }
            }
            long long bt = (long long)t * BSZ + gr;
            float2 uc = make_float2(0.f, 0.f);
            if (lane < 20) uc = *(const float2*)(&noise_c[bt * NCONST + 2 * lane]);
            float bc0 = sm[S_BCON + 2 * lane];
            float bc1 = sm[S_BCON + 2 * lane + 1];
            float la = (lane < 20) ? (co.x + bc0) : NEGINF;
            float lb = (lane < 20) ? (co.y + bc1) : NEGINF;
            float mc   = wmaxf(fmaxf(la, lb));
            float ec   = (lane < 20) ? (expf(la - mc) + expf(lb - mc)) : 0.f;
            float lsec = logf(wsumf(ec));
            float lpa = la - mc - lsec;
            float lpb = lb - mc - lsec;
            float sa = lpa + gumbelf(uc.x);
            float sb = lpb + gumbelf(uc.y);
            float s_l, lp_l; int i_l;
            if (sb > sa) { s_l = sb; i_l = 2 * lane + 1; lp_l = lpb; }
            else         { s_l = sa; i_l = 2 * lane;     lp_l = lpa; }
            wargmax(s_l, i_l, lp_l);
            cchoice = i_l; lp_c = lp_l;
        }

        if (lane == 0) {
            sm[S_LP + row] += lp_tok + (is_const ? lp_c : 0.f);
            out[gr * TT + pi] = (float)choice;
            if (is_const) out[OUT_CV + gr * TT + pi] = -10.f + 0.5f * (float)cchoice;
            int arity = (choice < 4) ? 2 : ((choice < 6) ? 1 : 0);
            int sp = si[SI_SP + row];
            if (arity == 2) {
                int wsp = sp < 7 ? sp : 7;
                si[SI_STK + row * 8 + wsp] = 2 * pi + 2;
            }
            int sp1 = sp + (arity == 2 ? 1 : 0);
            int nxt, sp2;
            if (arity != 0) { nxt = 2 * pi + 1; sp2 = sp1; }
            else {
                int ridx = sp1 - 1; if (ridx < 0) ridx = 0; if (ridx > 7) ridx = 7;
                nxt = (sp1 > 0) ? si[SI_STK + row * 8 + ridx] : -1;
                sp2 = (sp1 > 0) ? sp1 - 1 : 0;
            }
            if (nxt > TT - 1) nxt = -1;
            si[SI_POS + row]  = nxt;
            si[SI_SP + row]   = sp2;
            si[SI_ACTF + row] = (nxt >= 0) ? 1 : 0;
        }
        // fold chosen token code into W_ih accumulator (coalesced global reads)
        if (choice & 15) {
            int j0 = 4 * lane;
            float4 a = *(const float4*)(sm + S_ACC + row * HIDN + j0);
            int cb = 4 * pi;
#pragma unroll
            for (int b = 0; b < 4; b++) {
                if (choice & (1 << b)) {
                    float4 wv = *(const float4*)(&g_WihT[(cb + b) * HIDN + j0]);
                    a.x += wv.x; a.y += wv.y; a.z += wv.z; a.w += wv.w;
                }
            }
            *(float4*)(sm + S_ACC + row * HIDN + j0) = a;
        }
    }
}

__global__ void __launch_bounds__(NTH, 1)
rnn_main(const float* __restrict__ x,
         const float* __restrict__ noise_tok,
         const float* __restrict__ noise_c,
         const float* __restrict__ W_ih,
         const float* __restrict__ W_hh,
         const float* __restrict__ b_ih,
         const float* __restrict__ b_hh,
         const float* __restrict__ W_out,
         const float* __restrict__ b_out,
         const float* __restrict__ W_c,
         const float* __restrict__ b_c,
         float* __restrict__ out)
{
    extern __shared__ float sm[];
    int* si = (int*)(sm + S_NF);
    int tid = threadIdx.x;
    int gbase = blockIdx.x * RPB;
    int w = tid >> 5, lane = tid & 31;

    // stage W_hh transposed: sm[k*128+j] = W_hh[j*128+k]
    for (int idx = tid; idx < HIDN * HIDN; idx += NTH) {
        int j = idx / HIDN, k = idx % HIDN;
        sm[S_WHH + k * HIDN + j] = W_hh[idx];
    }
    // zero head regions + biases
    for (int idx = tid; idx < HIDN * 32; idx += NTH) sm[S_TOK + idx] = 0.f;
    for (int idx = tid; idx < HIDN * 64; idx += NTH) sm[S_CON + idx] = 0.f;
    if (tid < 32) sm[S_BTOK + tid] = 0.f;
    if (tid < 64) sm[S_BCON + tid] = 0.f;
    __syncthreads();
    for (int idx = tid; idx < NVOCAB * HIDN; idx += NTH) {
        int v = idx / HIDN, k = idx % HIDN;
        sm[S_TOK + k * 32 + v] = W_out[idx];
    }
    for (int idx = tid; idx < NCONST * HIDN; idx += NTH) {
        int c = idx / HIDN, k = idx % HIDN;
        sm[S_CON + k * 64 + c] = W_c[idx];
    }
    if (tid < NVOCAB) sm[S_BTOK + tid] = b_out[tid];
    if (tid < NCONST) sm[S_BCON + tid] = b_c[tid];

    // per-row init: acc = b_ih + b_hh + x @ W_ih[:,124:133].T ; h = 0
    int w4 = w * 4;
#pragma unroll
    for (int q = 0; q < 4; q++) {
        int row = w4 + q;
        int gr = gbase + row;
        int j0 = 4 * lane;
        float4 a;
        a.x = b_ih[j0 + 0] + b_hh[j0 + 0];
        a.y = b_ih[j0 + 1] + b_hh[j0 + 1];
        a.z = b_ih[j0 + 2] + b_hh[j0 + 2];
        a.w = b_ih[j0 + 3] + b_hh[j0 + 3];
        for (int f = 0; f < 9; f++) {
            float xv = x[gr * 9 + f];
            float4 wv = *(const float4*)(&g_WihT[(124 + f) * HIDN + j0]);
            a.x = fmaf(xv, wv.x, a.x);
            a.y = fmaf(xv, wv.y, a.y);
            a.z = fmaf(xv, wv.z, a.z);
            a.w = fmaf(xv, wv.w, a.w);
        }
        *(float4*)(sm + S_ACC + row * HIDN + j0) = a;
        *(float4*)(sm + S_H + row * HIDN + j0) = make_float4(0.f, 0.f, 0.f, 0.f);
    }
    if (lane < 4) {
        si[SI_POS + w4 + lane]  = 0;
        si[SI_SP + w4 + lane]   = 0;
        si[SI_ACTF + w4 + lane] = 1;
        sm[S_LP + w4 + lane]    = 0.f;
    }
    __syncthreads();

    // main loop: dense repack every step
    for (int t = 0; t < TT; t++) {
        if (w == 0) {
            int f0 = si[SI_ACTF + lane];
            int f1 = si[SI_ACTF + 32 + lane];
            unsigned m0 = __ballot_sync(FULLM, f0 != 0);
            unsigned m1 = __ballot_sync(FULLM, f1 != 0);
            int c0 = __popc(m0);
            unsigned lt = (1u << lane) - 1u;
            if (f0) si[SI_LIST + __popc(m0 & lt)] = lane;
            if (f1) si[SI_LIST + c0 + __popc(m1 & lt)] = 32 + lane;
            if (lane == 0) si[SI_CNT] = c0 + __popc(m1);
        }
        __syncthreads();
        int A = si[SI_CNT];
        if (A == 0) break;
        int base = 4 * w;
        if (base < A) {
            int cnt = A - base; if (cnt > 4) cnt = 4;
            int grp[4];
#pragma unroll
            for (int q = 0; q < 4; q++)
                grp[q] = si[SI_LIST + base + (q < cnt ? q : 0)];
            switch (cnt) {
                case 4: step_group<4>(sm, si, noise_tok, noise_c, out, t, gbase, grp, lane); break;
                case 3: step_group<3>(sm, si, noise_tok, noise_c, out, t, gbase, grp, lane); break;
                case 2: step_group<2>(sm, si, noise_tok, noise_c, out, t, gbase, grp, lane); break;
                default: step_group<1>(sm, si, noise_tok, noise_c, out, t, gbase, grp, lane); break;
            }
        }
        __syncthreads();
    }

    if (tid < RPB) {
        out[OUT_LP + gbase + tid] = sm[S_LP + tid];
    }
}

__global__ void prep_kernel(const float* __restrict__ W_ih)
{
    int i = blockIdx.x * blockDim.x + threadIdx.x;
    if (i < INSZ * HIDN) {
        int c = i / HIDN, j = i % HIDN;
        g_WihT[c * HIDN + j] = W_ih[j * INSZ + c];
    }
}

__global__ void init_out_kernel(float* __restrict__ out)
{
    float4* o4 = (float4*)out;
    const int n4 = OUT_TOT / 4;
    int stride = gridDim.x * blockDim.x;
    for (int i = blockIdx.x * blockDim.x + threadIdx.x; i < n4; i += stride) {
        float v = (i * 4 < OUT_CV) ? -1.f : 0.f;
        o4[i] = make_float4(v, v, v, v);
    }
}

extern "C" void kernel_launch(void* const* d_in, const int* in_sizes, int n_in,
                              void* d_out, int out_size)
{
    const float* x    = (const float*)d_in[0];
    const float* nt   = (const float*)d_in[1];
    const float* nc   = (const float*)d_in[2];
    const float* wih  = (const float*)d_in[3];
    const float* whh  = (const float*)d_in[4];
    const float* bih  = (const float*)d_in[5];
    const float* bhh  = (const float*)d_in[6];
    const float* wout = (const float*)d_in[7];
    const float* bout = (const float*)d_in[8];
    const float* wc   = (const float*)d_in[9];
    const float* bc   = (const float*)d_in[10];
    float* out = (float*)d_out;

    cudaFuncSetAttribute((const void*)rnn_main,
                         cudaFuncAttributeMaxDynamicSharedMemorySize, SMEM_BYTES);
    prep_kernel<<<(INSZ * HIDN + 255) / 256, 256>>>(wih);
    init_out_kernel<<<512, 256>>>(out);
    rnn_main<<<BSZ / RPB, NTH, SMEM_BYTES>>>(x, nt, nc, wih, whh, bih, bhh,
                                             wout, bout, wc, bc, out);
}

// round 3
// speedup vs baseline: 2.1301x; 1.8057x over previous
#include <cuda_runtime.h>
#include <math.h>

#define BSZ    65536
#define TT     31
#define HIDN   128
#define NVOCAB 19
#define NCONST 40
#define INSZ   133
#define SLOTS  64
#define NTH    512
#define NBLK   152

#define OUT_CV  2031616   // BSZ*TT
#define OUT_LP  4063232   // 2*BSZ*TT
#define OUT_TOT 4194304

typedef unsigned long long u64;

// shared float layout
#define S_WHHP 0            // u64[kp=64][j=128]  {W_hh^T[2kp][j], W_hh^T[2kp+1][j]}
#define S_TOKP 16384        // u64[kp=64][v=32]
#define S_CON  20480        // [k][64] const head, old layout
#define S_H    28672        // [64][128]
#define S_ACC  36864        // [64][128]
#define S_WX   45056        // [f=9][j=128]  W_ih cols 124..132
#define S_BSUM 46208        // 128  b_ih+b_hh
#define S_BTOK 46336        // 32
#define S_BCON 46368        // 64
#define S_LP   46432        // 64
#define S_NF   46496
// int region
#define SI_POS  0
#define SI_SP   64
#define SI_ACT  128
#define SI_T    192
#define SI_GROW 256
#define SI_STK  320         // 64 x 8
#define SI_LIST 832
#define SI_DEAD 896
#define SI_CNT  960         // [0]=A active, [1]=navail, [2]=base
#define SI_N    964
#define SMEM_BYTES ((S_NF + SI_N) * 4)

#define FULLM 0xffffffffu

__device__ float g_WihT[INSZ * HIDN];   // [c][j]
__device__ int   g_next;

__device__ __forceinline__ u64 ffma2(u64 a, u64 b, u64 c) {
    u64 d;
    asm("fma.rn.f32x2 %0, %1, %2, %3;" : "=l"(d) : "l"(a), "l"(b), "l"(c));
    return d;
}
__device__ __forceinline__ float f2lo(u64 v) { return __uint_as_float((unsigned)v); }
__device__ __forceinline__ float f2hi(u64 v) { return __uint_as_float((unsigned)(v >> 32)); }

__device__ __forceinline__ float gumbelf(float u) {
    float inner = -logf(u + 1e-9f);
    return -logf(inner + 1e-9f);
}
__device__ __forceinline__ float wmaxf(float v) {
#pragma unroll
    for (int o = 16; o; o >>= 1) v = fmaxf(v, __shfl_xor_sync(FULLM, v, o));
    return v;
}
__device__ __forceinline__ float wsumf(float v) {
#pragma unroll
    for (int o = 16; o; o >>= 1) v += __shfl_xor_sync(FULLM, v, o);
    return v;
}
__device__ __forceinline__ void wargmax(float& s, int& i, float& lp) {
#pragma unroll
    for (int o = 16; o; o >>= 1) {
        float s2 = __shfl_xor_sync(FULLM, s, o);
        int   i2 = __shfl_xor_sync(FULLM, i, o);
        float l2 = __shfl_xor_sync(FULLM, lp, o);
        if (s2 > s || (s2 == s && i2 < i)) { s = s2; i = i2; lp = l2; }
    }
}

template<int CNT>
__device__ __forceinline__ void step_group(float* sm, int* si,
                           const float* __restrict__ noise_tok,
                           const float* __restrict__ noise_c,
                           float* __restrict__ out,
                           const int* grp, int lane)
{
    int p[CNT], tt[CNT], gr[CNT];
    float u_t[CNT];
#pragma unroll
    for (int i = 0; i < CNT; i++) {
        int row = grp[i];
        p[i]  = si[SI_POS + row];
        tt[i] = si[SI_T + row];
        gr[i] = si[SI_GROW + row];
        long long bt = (long long)tt[i] * BSZ + gr[i];
        u_t[i] = (lane < NVOCAB) ? __ldg(&noise_tok[bt * NVOCAB + lane]) : 0.f;
    }

    // Phase A: z = W_hh * h via packed f32x2; lane owns j = lane + 32m
    u64 zp[CNT][4];
#pragma unroll
    for (int i = 0; i < CNT; i++)
#pragma unroll
        for (int m = 0; m < 4; m++) zp[i][m] = 0ull;
    const u64* WP = (const u64*)(sm + S_WHHP);
#pragma unroll 4
    for (int kp = 0; kp < 64; kp++) {
        u64 h2[CNT];
#pragma unroll
        for (int i = 0; i < CNT; i++)
            h2[i] = *(const u64*)(sm + S_H + grp[i] * HIDN + 2 * kp);
        const u64* wr = WP + kp * 128 + lane;
        u64 wv0 = wr[0], wv1 = wr[32], wv2 = wr[64], wv3 = wr[96];
#pragma unroll
        for (int i = 0; i < CNT; i++) {
            zp[i][0] = ffma2(h2[i], wv0, zp[i][0]);
            zp[i][1] = ffma2(h2[i], wv1, zp[i][1]);
            zp[i][2] = ffma2(h2[i], wv2, zp[i][2]);
            zp[i][3] = ffma2(h2[i], wv3, zp[i][3]);
        }
    }
    float hnew[CNT][4];
#pragma unroll
    for (int i = 0; i < CNT; i++) {
#pragma unroll
        for (int m = 0; m < 4; m++) {
            int j = lane + 32 * m;
            float z = f2lo(zp[i][m]) + f2hi(zp[i][m]);
            float a = sm[S_ACC + grp[i] * HIDN + j];
            hnew[i][m] = tanhf(z + a);
        }
    }
    __syncwarp();
#pragma unroll
    for (int i = 0; i < CNT; i++)
#pragma unroll
        for (int m = 0; m < 4; m++)
            sm[S_H + grp[i] * HIDN + lane + 32 * m] = hnew[i][m];
    __syncwarp();

    // Phase B: token head logits (lane = vocab index), packed
    u64 tkp[CNT];
#pragma unroll
    for (int i = 0; i < CNT; i++) tkp[i] = 0ull;
    const u64* TP = (const u64*)(sm + S_TOKP);
#pragma unroll 4
    for (int kp = 0; kp < 64; kp++) {
        u64 wv = TP[kp * 32 + lane];
#pragma unroll
        for (int i = 0; i < CNT; i++) {
            u64 h2 = *(const u64*)(sm + S_H + grp[i] * HIDN + 2 * kp);
            tkp[i] = ffma2(h2, wv, tkp[i]);
        }
    }
    float btok = sm[S_BTOK + lane];
    const float NEGINF = -INFINITY;

    // Phase C: per-row sampling + tree bookkeeping
#pragma unroll
    for (int i = 0; i < CNT; i++) {
        int row = grp[i];
        int pi  = p[i];

        float ltok = NEGINF;
        if (lane < NVOCAB) {
            ltok = f2lo(tkp[i]) + f2hi(tkp[i]) + btok;
            if (pi >= 15 && lane < 6) ltok = NEGINF;
        }
        float m   = wmaxf(ltok);
        float e   = (lane < NVOCAB) ? expf(ltok - m) : 0.f;
        float lse = logf(wsumf(e));
        float lpt = ltok - m - lse;
        float sc  = lpt + gumbelf(u_t[i]);
        int ci = lane; float lpw = lpt;
        wargmax(sc, ci, lpw);
        int choice = ci; float lp_tok = lpw;

        bool is_const = (choice == 18);
        float lp_c = 0.f; int cchoice = 0;
        if (is_const) {   // warp-uniform (choice identical across lanes)
            float2 co = make_float2(0.f, 0.f);
#pragma unroll 8
            for (int k4 = 0; k4 < 32; k4++) {
                float4 hv = *(const float4*)(sm + S_H + row * HIDN + 4 * k4);
#pragma unroll
                for (int b = 0; b < 4; b++) {
                    float2 wc = *(const float2*)(sm + S_CON + (4 * k4 + b) * 64 + 2 * lane);
                    float hk = (b == 0) ? hv.x : (b == 1) ? hv.y : (b == 2) ? hv.z : hv.w;
                    co.x = fmaf(hk, wc.x, co.x);
                    co.y = fmaf(hk, wc.y, co.y);
                }
            }
            long long bt = (long long)tt[i] * BSZ + gr[i];
            float2 uc = make_float2(0.f, 0.f);
            if (lane < 20) uc = *(const float2*)(&noise_c[bt * NCONST + 2 * lane]);
            float bc0 = sm[S_BCON + 2 * lane];
            float bc1 = sm[S_BCON + 2 * lane + 1];
            float la = (lane < 20) ? (co.x + bc0) : NEGINF;
            float lb = (lane < 20) ? (co.y + bc1) : NEGINF;
            float mc   = wmaxf(fmaxf(la, lb));
            float ec   = (lane < 20) ? (expf(la - mc) + expf(lb - mc)) : 0.f;
            float lsec = logf(wsumf(ec));
            float lpa = la - mc - lsec;
            float lpb = lb - mc - lsec;
            float sa = lpa + gumbelf(uc.x);
            float sb = lpb + gumbelf(uc.y);
            float s_l, lp_l; int i_l;
            if (sb > sa) { s_l = sb; i_l = 2 * lane + 1; lp_l = lpb; }
            else         { s_l = sa; i_l = 2 * lane;     lp_l = lpa; }
            wargmax(s_l, i_l, lp_l);
            cchoice = i_l; lp_c = lp_l;
        }

        if (lane == 0) {
            float lpn = sm[S_LP + row] + lp_tok + (is_const ? lp_c : 0.f);
            out[gr[i] * TT + pi] = (float)choice;
            if (is_const) out[OUT_CV + gr[i] * TT + pi] = -10.f + 0.5f * (float)cchoice;
            int arity = (choice < 4) ? 2 : ((choice < 6) ? 1 : 0);
            int sp = si[SI_SP + row];
            if (arity == 2) {
                int wsp = sp < 7 ? sp : 7;
                si[SI_STK + row * 8 + wsp] = 2 * pi + 2;
            }
            int sp1 = sp + (arity == 2 ? 1 : 0);
            int nxt, sp2;
            if (arity != 0) { nxt = 2 * pi + 1; sp2 = sp1; }
            else {
                int ridx = sp1 - 1; if (ridx < 0) ridx = 0; if (ridx > 7) ridx = 7;
                nxt = (sp1 > 0) ? si[SI_STK + row * 8 + ridx] : -1;
                sp2 = (sp1 > 0) ? sp1 - 1 : 0;
            }
            if (nxt > TT - 1) nxt = -1;
            if (nxt >= 0) {
                sm[S_LP + row]  = lpn;
                si[SI_POS + row] = nxt;
                si[SI_SP + row]  = sp2;
                si[SI_T + row]   = tt[i] + 1;
            } else {
                si[SI_ACT + row] = 0;
                out[OUT_LP + gr[i]] = lpn;   // row finished: emit log-prob
            }
        }
        // fold chosen token code into W_ih accumulator
        if (choice & 15) {
            int cb = 4 * pi;
#pragma unroll
            for (int m = 0; m < 4; m++) {
                int j = lane + 32 * m;
                float a = sm[S_ACC + row * HIDN + j];
#pragma unroll
                for (int b = 0; b < 4; b++)
                    if (choice & (1 << b))
                        a += __ldg(&g_WihT[(cb + b) * HIDN + j]);
                sm[S_ACC + row * HIDN + j] = a;
            }
        }
    }
}

__global__ void __launch_bounds__(NTH, 1)
rnn_main(const float* __restrict__ x,
         const float* __restrict__ noise_tok,
         const float* __restrict__ noise_c,
         const float* __restrict__ W_ih,
         const float* __restrict__ W_hh,
         const float* __restrict__ b_ih,
         const float* __restrict__ b_hh,
         const float* __restrict__ W_out,
         const float* __restrict__ b_out,
         const float* __restrict__ W_c,
         const float* __restrict__ b_c,
         float* __restrict__ out)
{
    extern __shared__ float sm[];
    int* si = (int*)(sm + S_NF);
    int tid = threadIdx.x;
    int w = tid >> 5, lane = tid & 31;

    // ---- stage weights ----
    // W_hh k-pairs: dst[kp*128 + j] = {W_hh[j][2kp], W_hh[j][2kp+1]}
    {
        const u64* src = (const u64*)W_hh;   // [j][64]
        u64* dst = (u64*)(sm + S_WHHP);
        for (int idx = tid; idx < 64 * 128; idx += NTH) {
            int j = idx >> 6, kp = idx & 63;
            dst[kp * 128 + j] = src[idx];
        }
    }
    // token head k-pairs (zero-pad vocab 19..31)
    {
        u64* dst = (u64*)(sm + S_TOKP);
        for (int idx = tid; idx < 64 * 32; idx += NTH) dst[idx] = 0ull;
        __syncthreads();
        const u64* src = (const u64*)W_out;  // [v][64]
        for (int idx = tid; idx < NVOCAB * 64; idx += NTH) {
            int v = idx >> 6, kp = idx & 63;
            dst[kp * 32 + v] = src[idx];
        }
    }
    // const head old layout [k][64], zero padded
    for (int idx = tid; idx < HIDN * 64; idx += NTH) sm[S_CON + idx] = 0.f;
    __syncthreads();
    for (int idx = tid; idx < NCONST * HIDN; idx += NTH) {
        int c = idx / HIDN, k = idx % HIDN;
        sm[S_CON + k * 64 + c] = W_c[idx];
    }
    // x-part of W_ih, bias sum, head biases
    for (int idx = tid; idx < 9 * HIDN; idx += NTH) {
        int f = idx >> 7, j = idx & 127;
        sm[S_WX + f * 128 + j] = W_ih[j * INSZ + 124 + f];
    }
    if (tid < HIDN) sm[S_BSUM + tid] = b_ih[tid] + b_hh[tid];
    if (tid < 32) sm[S_BTOK + tid] = (tid < NVOCAB) ? b_out[tid] : 0.f;
    if (tid < 64) sm[S_BCON + tid] = (tid < NCONST) ? b_c[tid] : 0.f;
    if (tid < SLOTS) si[SI_ACT + tid] = 0;
    __syncthreads();

    // ---- persistent work loop ----
    for (;;) {
        if (w == 0) {
            int s0 = lane, s1 = 32 + lane;
            int f0 = si[SI_ACT + s0];
            int f1 = si[SI_ACT + s1];
            unsigned d0m = __ballot_sync(FULLM, !f0);
            unsigned d1m = __ballot_sync(FULLM, !f1);
            int nd0 = __popc(d0m);
            int nd = nd0 + __popc(d1m);
            int base = 0;
            if (lane == 0 && nd > 0) base = atomicAdd(&g_next, nd);
            base = __shfl_sync(FULLM, base, 0);
            int navail = BSZ - base;
            if (navail < 0) navail = 0;
            if (navail > nd) navail = nd;
            unsigned lt = (1u << lane) - 1u;
            int q0 = __popc(d0m & lt);
            int q1 = nd0 + __popc(d1m & lt);
            if (!f0) si[SI_DEAD + q0] = s0;
            if (!f1) si[SI_DEAD + q1] = s1;
            int a0 = f0 || (q0 < navail);
            int a1 = f1 || (q1 < navail);
            unsigned am0 = __ballot_sync(FULLM, a0);
            unsigned am1 = __ballot_sync(FULLM, a1);
            int c0 = __popc(am0);
            if (a0) si[SI_LIST + __popc(am0 & lt)] = s0;
            if (a1) si[SI_LIST + c0 + __popc(am1 & lt)] = s1;
            if (lane == 0) {
                si[SI_CNT]     = c0 + __popc(am1);
                si[SI_CNT + 1] = navail;
                si[SI_CNT + 2] = base;
            }
        }
        __syncthreads();
        int A = si[SI_CNT];
        int navail = si[SI_CNT + 1];
        int rbase  = si[SI_CNT + 2];
        if (A == 0) break;

        // refill dead slots with fresh rows
        for (int q = w; q < navail; q += 16) {
            int slot = si[SI_DEAD + q];
            int gr = rbase + q;
            float xv[9];
#pragma unroll
            for (int f = 0; f < 9; f++) xv[f] = __ldg(&x[gr * 9 + f]);
#pragma unroll
            for (int m = 0; m < 4; m++) {
                int j = lane + 32 * m;
                float a = sm[S_BSUM + j];
#pragma unroll
                for (int f = 0; f < 9; f++) a = fmaf(xv[f], sm[S_WX + f * 128 + j], a);
                sm[S_ACC + slot * HIDN + j] = a;
                sm[S_H + slot * HIDN + j] = 0.f;
            }
            if (lane == 0) {
                si[SI_POS + slot]  = 0;
                si[SI_SP + slot]   = 0;
                si[SI_T + slot]    = 0;
                si[SI_ACT + slot]  = 1;
                si[SI_GROW + slot] = gr;
                sm[S_LP + slot]    = 0.f;
            }
        }
        __syncthreads();

        int sbase = 4 * w;
        if (sbase < A) {
            int cnt = A - sbase; if (cnt > 4) cnt = 4;
            int grp[4];
#pragma unroll
            for (int q = 0; q < 4; q++)
                grp[q] = si[SI_LIST + sbase + (q < cnt ? q : 0)];
            switch (cnt) {
                case 4: step_group<4>(sm, si, noise_tok, noise_c, out, grp, lane); break;
                case 3: step_group<3>(sm, si, noise_tok, noise_c, out, grp, lane); break;
                case 2: step_group<2>(sm, si, noise_tok, noise_c, out, grp, lane); break;
                default: step_group<1>(sm, si, noise_tok, noise_c, out, grp, lane); break;
            }
        }
        __syncthreads();
    }
}

__global__ void prep_kernel(const float* __restrict__ W_ih)
{
    int i = blockIdx.x * blockDim.x + threadIdx.x;
    if (i == 0) g_next = 0;
    if (i < INSZ * HIDN) {
        int c = i / HIDN, j = i % HIDN;
        g_WihT[c * HIDN + j] = W_ih[j * INSZ + c];
    }
}

__global__ void init_out_kernel(float* __restrict__ out)
{
    float4* o4 = (float4*)out;
    const int n4 = OUT_TOT / 4;
    int stride = gridDim.x * blockDim.x;
    for (int i = blockIdx.x * blockDim.x + threadIdx.x; i < n4; i += stride) {
        float v = (i * 4 < OUT_CV) ? -1.f : 0.f;
        o4[i] = make_float4(v, v, v, v);
    }
}

extern "C" void kernel_launch(void* const* d_in, const int* in_sizes, int n_in,
                              void* d_out, int out_size)
{
    const float* x    = (const float*)d_in[0];
    const float* nt   = (const float*)d_in[1];
    const float* nc   = (const float*)d_in[2];
    const float* wih  = (const float*)d_in[3];
    const float* whh  = (const float*)d_in[4];
    const float* bih  = (const float*)d_in[5];
    const float* bhh  = (const float*)d_in[6];
    const float* wout = (const float*)d_in[7];
    const float* bout = (const float*)d_in[8];
    const float* wc   = (const float*)d_in[9];
    const float* bc   = (const float*)d_in[10];
    float* out = (float*)d_out;

    cudaFuncSetAttribute((const void*)rnn_main,
                         cudaFuncAttributeMaxDynamicSharedMemorySize, SMEM_BYTES);
    prep_kernel<<<(INSZ * HIDN + 255) / 256, 256>>>(wih);
    init_out_kernel<<<512, 256>>>(out);
    rnn_main<<<NBLK, NTH, SMEM_BYTES>>>(x, nt, nc, wih, whh, bih, bhh,
                                        wout, bout, wc, bc, out);
}

// round 4
// speedup vs baseline: 2.2157x; 1.0402x over previous
#include <cuda_runtime.h>
#include <math.h>

#define BSZ    65536
#define TT     31
#define HIDN   128
#define NVOCAB 19
#define NCONST 40
#define INSZ   133
#define SLOTS  64
#define NTH    512
#define NBLK   152

#define OUT_CV  2031616   // BSZ*TT
#define OUT_LP  4063232   // 2*BSZ*TT
#define OUT_TOT 4194304

typedef unsigned long long u64;

// shared float layout
#define S_WHHP 0            // u64[kp=64][j=128]  {W_hh^T[2kp][j], W_hh^T[2kp+1][j]}
#define S_TOKP 16384        // u64[kp=64][v=32]
#define S_CON  20480        // [k][64] const head
#define S_H    28672        // [64][128]
#define S_ACC  36864        // [64][128]
#define S_WX   45056        // [f=9][j=128]
#define S_BSUM 46208        // 128
#define S_BTOK 46336        // 32
#define S_BCON 46368        // 64
#define S_LP   46432        // 64
#define S_NF   46496
// int region
#define SI_POS  0
#define SI_SP   64
#define SI_ACT  128
#define SI_T    192
#define SI_GROW 256
#define SI_STK  320         // 64 x 8
#define SI_LIST 832
#define SI_DEAD 896
#define SI_CNT  960
#define SI_N    964
#define SMEM_BYTES ((S_NF + SI_N) * 4)

#define FULLM 0xffffffffu

__device__ float g_WihT[INSZ * HIDN];   // [c][j]
__device__ int   g_next;

__device__ __forceinline__ u64 ffma2(u64 a, u64 b, u64 c) {
    u64 d;
    asm("fma.rn.f32x2 %0, %1, %2, %3;" : "=l"(d) : "l"(a), "l"(b), "l"(c));
    return d;
}
__device__ __forceinline__ float f2lo(u64 v) { return __uint_as_float((unsigned)v); }
__device__ __forceinline__ float f2hi(u64 v) { return __uint_as_float((unsigned)(v >> 32)); }

__device__ __forceinline__ float gumbelf(float u) {
    float inner = -logf(u + 1e-9f);
    return -logf(inner + 1e-9f);
}
__device__ __forceinline__ float wmaxf(float v) {
#pragma unroll
    for (int o = 16; o; o >>= 1) v = fmaxf(v, __shfl_xor_sync(FULLM, v, o));
    return v;
}
__device__ __forceinline__ float wsumf(float v) {
#pragma unroll
    for (int o = 16; o; o >>= 1) v += __shfl_xor_sync(FULLM, v, o);
    return v;
}
__device__ __forceinline__ void wargmax(float& s, int& i, float& lp) {
#pragma unroll
    for (int o = 16; o; o >>= 1) {
        float s2 = __shfl_xor_sync(FULLM, s, o);
        int   i2 = __shfl_xor_sync(FULLM, i, o);
        float l2 = __shfl_xor_sync(FULLM, lp, o);
        if (s2 > s || (s2 == s && i2 < i)) { s = s2; i = i2; lp = l2; }
    }
}

template<int CNT>
__device__ __forceinline__ void step_group(float* sm, int* si,
                           const float* __restrict__ noise_tok,
                           const float* __restrict__ noise_c,
                           float* __restrict__ out,
                           const int* grp, int lane)
{
    int p[CNT], tt[CNT], gr[CNT];
    float g_t[CNT];
#pragma unroll
    for (int i = 0; i < CNT; i++) {
        int row = grp[i];
        p[i]  = si[SI_POS + row];
        tt[i] = si[SI_T + row];
        gr[i] = si[SI_GROW + row];
        long long bt = (long long)tt[i] * BSZ + gr[i];
        float u = (lane < NVOCAB) ? __ldg(&noise_tok[bt * NVOCAB + lane]) : 0.5f;
        g_t[i] = gumbelf(u);   // hoisted: 2 logf chains overlap the GEMV below
    }

    // Phase A: z = W_hh * h via packed f32x2; lane owns j = lane + 32m
    u64 zp[CNT][4];
#pragma unroll
    for (int i = 0; i < CNT; i++)
#pragma unroll
        for (int m = 0; m < 4; m++) zp[i][m] = 0ull;
    const u64* WP = (const u64*)(sm + S_WHHP);
#pragma unroll 4
    for (int kp = 0; kp < 64; kp++) {
        u64 h2[CNT];
#pragma unroll
        for (int i = 0; i < CNT; i++)
            h2[i] = *(const u64*)(sm + S_H + grp[i] * HIDN + 2 * kp);
        const u64* wr = WP + kp * 128 + lane;
        u64 wv0 = wr[0], wv1 = wr[32], wv2 = wr[64], wv3 = wr[96];
#pragma unroll
        for (int i = 0; i < CNT; i++) {
            zp[i][0] = ffma2(h2[i], wv0, zp[i][0]);
            zp[i][1] = ffma2(h2[i], wv1, zp[i][1]);
            zp[i][2] = ffma2(h2[i], wv2, zp[i][2]);
            zp[i][3] = ffma2(h2[i], wv3, zp[i][3]);
        }
    }
    float hnew[CNT][4];
#pragma unroll
    for (int i = 0; i < CNT; i++) {
#pragma unroll
        for (int m = 0; m < 4; m++) {
            int j = lane + 32 * m;
            float z = f2lo(zp[i][m]) + f2hi(zp[i][m]);
            float a = sm[S_ACC + grp[i] * HIDN + j];
            hnew[i][m] = tanhf(z + a);
        }
    }
    __syncwarp();
#pragma unroll
    for (int i = 0; i < CNT; i++)
#pragma unroll
        for (int m = 0; m < 4; m++)
            sm[S_H + grp[i] * HIDN + lane + 32 * m] = hnew[i][m];
    __syncwarp();

    // Phase B: token head logits (lane = vocab index), packed
    u64 tkp[CNT];
#pragma unroll
    for (int i = 0; i < CNT; i++) tkp[i] = 0ull;
    const u64* TP = (const u64*)(sm + S_TOKP);
#pragma unroll 4
    for (int kp = 0; kp < 64; kp++) {
        u64 wv = TP[kp * 32 + lane];
#pragma unroll
        for (int i = 0; i < CNT; i++) {
            u64 h2 = *(const u64*)(sm + S_H + grp[i] * HIDN + 2 * kp);
            tkp[i] = ffma2(h2, wv, tkp[i]);
        }
    }
    float btok = sm[S_BTOK + lane];
    const float NEGINF = -INFINITY;

    // Phase C1: batched softmax + Gumbel argmax across rows (4-way ILP on chains)
    float ltok[CNT];
#pragma unroll
    for (int i = 0; i < CNT; i++) {
        float l = NEGINF;
        if (lane < NVOCAB) {
            l = f2lo(tkp[i]) + f2hi(tkp[i]) + btok;
            if (p[i] >= 15 && lane < 6) l = NEGINF;
        }
        ltok[i] = l;
    }
    float mx[CNT];
#pragma unroll
    for (int i = 0; i < CNT; i++) mx[i] = ltok[i];
#pragma unroll
    for (int o = 16; o; o >>= 1)
#pragma unroll
        for (int i = 0; i < CNT; i++)
            mx[i] = fmaxf(mx[i], __shfl_xor_sync(FULLM, mx[i], o));
    float sme[CNT];
#pragma unroll
    for (int i = 0; i < CNT; i++)
        sme[i] = (lane < NVOCAB) ? expf(ltok[i] - mx[i]) : 0.f;
#pragma unroll
    for (int o = 16; o; o >>= 1)
#pragma unroll
        for (int i = 0; i < CNT; i++)
            sme[i] += __shfl_xor_sync(FULLM, sme[i], o);
    float lpt[CNT], sc[CNT], lpw[CNT];
    int ci[CNT];
#pragma unroll
    for (int i = 0; i < CNT; i++) {
        float lse = logf(sme[i]);
        lpt[i] = ltok[i] - mx[i] - lse;
        sc[i]  = lpt[i] + g_t[i];
        ci[i]  = lane;
        lpw[i] = lpt[i];
    }
#pragma unroll
    for (int o = 16; o; o >>= 1) {
#pragma unroll
        for (int i = 0; i < CNT; i++) {
            float s2 = __shfl_xor_sync(FULLM, sc[i], o);
            int   i2 = __shfl_xor_sync(FULLM, ci[i], o);
            float l2 = __shfl_xor_sync(FULLM, lpw[i], o);
            if (s2 > sc[i] || (s2 == sc[i] && i2 < ci[i])) {
                sc[i] = s2; ci[i] = i2; lpw[i] = l2;
            }
        }
    }

    // Phase C2: per-row const head (rare, warp-uniform) + bookkeeping
#pragma unroll
    for (int i = 0; i < CNT; i++) {
        int row = grp[i];
        int pi  = p[i];
        int choice = ci[i];
        float lp_tok = lpw[i];

        bool is_const = (choice == 18);
        float lp_c = 0.f; int cchoice = 0;
        if (is_const) {
            float2 co = make_float2(0.f, 0.f);
#pragma unroll 8
            for (int k4 = 0; k4 < 32; k4++) {
                float4 hv = *(const float4*)(sm + S_H + row * HIDN + 4 * k4);
#pragma unroll
                for (int b = 0; b < 4; b++) {
                    float2 wc = *(const float2*)(sm + S_CON + (4 * k4 + b) * 64 + 2 * lane);
                    float hk = (b == 0) ? hv.x : (b == 1) ? hv.y : (b == 2) ? hv.z : hv.w;
                    co.x = fmaf(hk, wc.x, co.x);
                    co.y = fmaf(hk, wc.y, co.y);
                }
            }
            long long bt = (long long)tt[i] * BSZ + gr[i];
            float2 uc = make_float2(0.f, 0.f);
            if (lane < 20) uc = *(const float2*)(&noise_c[bt * NCONST + 2 * lane]);
            float bc0 = sm[S_BCON + 2 * lane];
            float bc1 = sm[S_BCON + 2 * lane + 1];
            float la = (lane < 20) ? (co.x + bc0) : NEGINF;
            float lb = (lane < 20) ? (co.y + bc1) : NEGINF;
            float mc   = wmaxf(fmaxf(la, lb));
            float ec   = (lane < 20) ? (expf(la - mc) + expf(lb - mc)) : 0.f;
            float lsec = logf(wsumf(ec));
            float lpa = la - mc - lsec;
            float lpb = lb - mc - lsec;
            float sa = lpa + gumbelf(uc.x);
            float sb = lpb + gumbelf(uc.y);
            float s_l, lp_l; int i_l;
            if (sb > sa) { s_l = sb; i_l = 2 * lane + 1; lp_l = lpb; }
            else         { s_l = sa; i_l = 2 * lane;     lp_l = lpa; }
            wargmax(s_l, i_l, lp_l);
            cchoice = i_l; lp_c = lp_l;
        }

        if (lane == 0) {
            float lpn = sm[S_LP + row] + lp_tok + (is_const ? lp_c : 0.f);
            out[gr[i] * TT + pi] = (float)choice;
            if (is_const) out[OUT_CV + gr[i] * TT + pi] = -10.f + 0.5f * (float)cchoice;
            int arity = (choice < 4) ? 2 : ((choice < 6) ? 1 : 0);
            int sp = si[SI_SP + row];
            if (arity == 2) {
                int wsp = sp < 7 ? sp : 7;
                si[SI_STK + row * 8 + wsp] = 2 * pi + 2;
            }
            int sp1 = sp + (arity == 2 ? 1 : 0);
            int nxt, sp2;
            if (arity != 0) { nxt = 2 * pi + 1; sp2 = sp1; }
            else {
                int ridx = sp1 - 1; if (ridx < 0) ridx = 0; if (ridx > 7) ridx = 7;
                nxt = (sp1 > 0) ? si[SI_STK + row * 8 + ridx] : -1;
                sp2 = (sp1 > 0) ? sp1 - 1 : 0;
            }
            if (nxt > TT - 1) nxt = -1;
            if (nxt >= 0) {
                sm[S_LP + row]   = lpn;
                si[SI_POS + row] = nxt;
                si[SI_SP + row]  = sp2;
                si[SI_T + row]   = tt[i] + 1;
            } else {
                si[SI_ACT + row] = 0;
                out[OUT_LP + gr[i]] = lpn;
            }
        }
        // fold chosen token code into W_ih accumulator
        if (choice & 15) {
            int cb = 4 * p[i];
#pragma unroll
            for (int m = 0; m < 4; m++) {
                int j = lane + 32 * m;
                float a = sm[S_ACC + row * HIDN + j];
#pragma unroll
                for (int b = 0; b < 4; b++)
                    if (choice & (1 << b))
                        a += __ldg(&g_WihT[(cb + b) * HIDN + j]);
                sm[S_ACC + row * HIDN + j] = a;
            }
        }
    }
}

__global__ void __launch_bounds__(NTH, 1)
rnn_main(const float* __restrict__ x,
         const float* __restrict__ noise_tok,
         const float* __restrict__ noise_c,
         const float* __restrict__ W_ih,
         const float* __restrict__ W_hh,
         const float* __restrict__ b_ih,
         const float* __restrict__ b_hh,
         const float* __restrict__ W_out,
         const float* __restrict__ b_out,
         const float* __restrict__ W_c,
         const float* __restrict__ b_c,
         float* __restrict__ out)
{
    extern __shared__ float sm[];
    int* si = (int*)(sm + S_NF);
    int tid = threadIdx.x;
    int w = tid >> 5, lane = tid & 31;

    // ---- stage weights ----
    {
        const u64* src = (const u64*)W_hh;   // [j][64]
        u64* dst = (u64*)(sm + S_WHHP);
        for (int idx = tid; idx < 64 * 128; idx += NTH) {
            int j = idx >> 6, kp = idx & 63;
            dst[kp * 128 + j] = src[idx];
        }
    }
    {
        u64* dst = (u64*)(sm + S_TOKP);
        for (int idx = tid; idx < 64 * 32; idx += NTH) dst[idx] = 0ull;
        __syncthreads();
        const u64* src = (const u64*)W_out;  // [v][64]
        for (int idx = tid; idx < NVOCAB * 64; idx += NTH) {
            int v = idx >> 6, kp = idx & 63;
            dst[kp * 32 + v] = src[idx];
        }
    }
    for (int idx = tid; idx < HIDN * 64; idx += NTH) sm[S_CON + idx] = 0.f;
    __syncthreads();
    for (int idx = tid; idx < NCONST * HIDN; idx += NTH) {
        int c = idx / HIDN, k = idx % HIDN;
        sm[S_CON + k * 64 + c] = W_c[idx];
    }
    for (int idx = tid; idx < 9 * HIDN; idx += NTH) {
        int f = idx >> 7, j = idx & 127;
        sm[S_WX + f * 128 + j] = W_ih[j * INSZ + 124 + f];
    }
    if (tid < HIDN) sm[S_BSUM + tid] = b_ih[tid] + b_hh[tid];
    if (tid < 32) sm[S_BTOK + tid] = (tid < NVOCAB) ? b_out[tid] : 0.f;
    if (tid < 64) sm[S_BCON + tid] = (tid < NCONST) ? b_c[tid] : 0.f;
    if (tid < SLOTS) si[SI_ACT + tid] = 0;
    __syncthreads();

    // ---- persistent work loop ----
    for (;;) {
        if (w == 0) {
            int s0 = lane, s1 = 32 + lane;
            int f0 = si[SI_ACT + s0];
            int f1 = si[SI_ACT + s1];
            unsigned d0m = __ballot_sync(FULLM, !f0);
            unsigned d1m = __ballot_sync(FULLM, !f1);
            int nd0 = __popc(d0m);
            int nd = nd0 + __popc(d1m);
            int base = 0;
            if (lane == 0 && nd > 0) base = atomicAdd(&g_next, nd);
            base = __shfl_sync(FULLM, base, 0);
            int navail = BSZ - base;
            if (navail < 0) navail = 0;
            if (navail > nd) navail = nd;
            unsigned lt = (1u << lane) - 1u;
            int q0 = __popc(d0m & lt);
            int q1 = nd0 + __popc(d1m & lt);
            if (!f0) si[SI_DEAD + q0] = s0;
            if (!f1) si[SI_DEAD + q1] = s1;
            int a0 = f0 || (q0 < navail);
            int a1 = f1 || (q1 < navail);
            unsigned am0 = __ballot_sync(FULLM, a0);
            unsigned am1 = __ballot_sync(FULLM, a1);
            int c0 = __popc(am0);
            if (a0) si[SI_LIST + __popc(am0 & lt)] = s0;
            if (a1) si[SI_LIST + c0 + __popc(am1 & lt)] = s1;
            if (lane == 0) {
                si[SI_CNT]     = c0 + __popc(am1);
                si[SI_CNT + 1] = navail;
                si[SI_CNT + 2] = base;
            }
        }
        __syncthreads();
        int A = si[SI_CNT];
        int navail = si[SI_CNT + 1];
        int rbase  = si[SI_CNT + 2];
        if (A == 0) break;

        for (int q = w; q < navail; q += 16) {
            int slot = si[SI_DEAD + q];
            int gr = rbase + q;
            float xv[9];
#pragma unroll
            for (int f = 0; f < 9; f++) xv[f] = __ldg(&x[gr * 9 + f]);
#pragma unroll
            for (int m = 0; m < 4; m++) {
                int j = lane + 32 * m;
                float a = sm[S_BSUM + j];
#pragma unroll
                for (int f = 0; f < 9; f++) a = fmaf(xv[f], sm[S_WX + f * 128 + j], a);
                sm[S_ACC + slot * HIDN + j] = a;
                sm[S_H + slot * HIDN + j] = 0.f;
            }
            if (lane == 0) {
                si[SI_POS + slot]  = 0;
                si[SI_SP + slot]   = 0;
                si[SI_T + slot]    = 0;
                si[SI_ACT + slot]  = 1;
                si[SI_GROW + slot] = gr;
                sm[S_LP + slot]    = 0.f;
            }
        }
        __syncthreads();

        int sbase = 4 * w;
        if (sbase < A) {
            int cnt = A - sbase; if (cnt > 4) cnt = 4;
            int grp[4];
#pragma unroll
            for (int q = 0; q < 4; q++)
                grp[q] = si[SI_LIST + sbase + (q < cnt ? q : 0)];
            switch (cnt) {
                case 4: step_group<4>(sm, si, noise_tok, noise_c, out, grp, lane); break;
                case 3: step_group<3>(sm, si, noise_tok, noise_c, out, grp, lane); break;
                case 2: step_group<2>(sm, si, noise_tok, noise_c, out, grp, lane); break;
                default: step_group<1>(sm, si, noise_tok, noise_c, out, grp, lane); break;
            }
        }
        __syncthreads();
    }
}

// merged prep + output-init (2 launches per call -> rnn_main lands in the ncu window)
__global__ void setup_kernel(const float* __restrict__ W_ih, float* __restrict__ out)
{
    int i = blockIdx.x * blockDim.x + threadIdx.x;
    if (i == 0) g_next = 0;
    if (i < INSZ * HIDN) {
        int c = i / HIDN, j = i % HIDN;
        g_WihT[c * HIDN + j] = W_ih[j * INSZ + c];
    }
    float4* o4 = (float4*)out;
    const int n4 = OUT_TOT / 4;
    int stride = gridDim.x * blockDim.x;
    for (int k = i; k < n4; k += stride) {
        float v = (k * 4 < OUT_CV) ? -1.f : 0.f;
        o4[k] = make_float4(v, v, v, v);
    }
}

extern "C" void kernel_launch(void* const* d_in, const int* in_sizes, int n_in,
                              void* d_out, int out_size)
{
    const float* x    = (const float*)d_in[0];
    const float* nt   = (const float*)d_in[1];
    const float* nc   = (const float*)d_in[2];
    const float* wih  = (const float*)d_in[3];
    const float* whh  = (const float*)d_in[4];
    const float* bih  = (const float*)d_in[5];
    const float* bhh  = (const float*)d_in[6];
    const float* wout = (const float*)d_in[7];
    const float* bout = (const float*)d_in[8];
    const float* wc   = (const float*)d_in[9];
    const float* bc   = (const float*)d_in[10];
    float* out = (float*)d_out;

    cudaFuncSetAttribute((const void*)rnn_main,
                         cudaFuncAttributeMaxDynamicSharedMemorySize, SMEM_BYTES);
    setup_kernel<<<512, 256>>>(wih, out);
    rnn_main<<<NBLK, NTH, SMEM_BYTES>>>(x, nt, nc, wih, whh, bih, bhh,
                                        wout, bout, wc, bc, out);
}

// round 5
// speedup vs baseline: 2.4227x; 1.0934x over previous
#include <cuda_runtime.h>
#include <math.h>

#define BSZ    65536
#define TT     31
#define HIDN   128
#define NVOCAB 19
#define NCONST 40
#define INSZ   133
#define SLOTS  64
#define NTH    512
#define NBLK   152

#define OUT_CV  2031616   // BSZ*TT
#define OUT_LP  4063232   // 2*BSZ*TT
#define OUT_TOT 4194304

typedef unsigned long long u64;

// shared float layout
#define S_WHH  0            // float4[kq=32][j=128]: {W_hh[j][4kq..4kq+3]}
#define S_TOKP 16384        // float4[kq=32][v=32]:  {W_out[v][4kq..4kq+3]}
#define S_CON  20480        // [k][64] const head
#define S_H    28672        // [64][128]
#define S_ACC  36864        // [64][128]
#define S_WX   45056        // [f=9][j=128]
#define S_BSUM 46208        // 128
#define S_BTOK 46336        // 32
#define S_BCON 46368        // 64
#define S_LP   46432        // 64
#define S_NF   46496
// int region
#define SI_POS  0
#define SI_SP   64
#define SI_ACT  128
#define SI_T    192
#define SI_GROW 256
#define SI_STK  320         // 64 x 8
#define SI_LIST 832
#define SI_DEAD 896
#define SI_CNT  960         // [0]=A [1]=navail [2]=base [3]=oldc
#define SI_N    968
#define SMEM_BYTES ((S_NF + SI_N) * 4)

#define FULLM 0xffffffffu

__device__ float g_WihT[INSZ * HIDN];   // [c][j]
__device__ int   g_next;

__device__ __forceinline__ u64 ffma2(u64 a, u64 b, u64 c) {
    u64 d;
    asm("fma.rn.f32x2 %0, %1, %2, %3;" : "=l"(d) : "l"(a), "l"(b), "l"(c));
    return d;
}
__device__ __forceinline__ float f2lo(u64 v) { return __uint_as_float((unsigned)v); }
__device__ __forceinline__ float f2hi(u64 v) { return __uint_as_float((unsigned)(v >> 32)); }

// one LDS.128 fetching two packed f32x2 operands
__device__ __forceinline__ void lds2(u64& a, u64& b, const float* p) {
    unsigned addr = (unsigned)__cvta_generic_to_shared(p);
    asm("ld.shared.v2.b64 {%0, %1}, [%2];" : "=l"(a), "=l"(b) : "r"(addr));
}

__device__ __forceinline__ float gumbelf(float u) {
    float inner = -logf(u + 1e-9f);
    return -logf(inner + 1e-9f);
}
__device__ __forceinline__ float wmaxf(float v) {
#pragma unroll
    for (int o = 16; o; o >>= 1) v = fmaxf(v, __shfl_xor_sync(FULLM, v, o));
    return v;
}
__device__ __forceinline__ float wsumf(float v) {
#pragma unroll
    for (int o = 16; o; o >>= 1) v += __shfl_xor_sync(FULLM, v, o);
    return v;
}
__device__ __forceinline__ void wargmax(float& s, int& i, float& lp) {
#pragma unroll
    for (int o = 16; o; o >>= 1) {
        float s2 = __shfl_xor_sync(FULLM, s, o);
        int   i2 = __shfl_xor_sync(FULLM, i, o);
        float l2 = __shfl_xor_sync(FULLM, lp, o);
        if (s2 > s || (s2 == s && i2 < i)) { s = s2; i = i2; lp = l2; }
    }
}

template<int CNT, bool FRESH>
__device__ __forceinline__ void step_group(float* sm, int* si,
                           const float* __restrict__ noise_tok,
                           const float* __restrict__ noise_c,
                           float* __restrict__ out,
                           const int* grp, int lane)
{
    int p[CNT], tt[CNT], gr[CNT];
    float g_t[CNT];
#pragma unroll
    for (int i = 0; i < CNT; i++) {
        int row = grp[i];
        p[i]  = si[SI_POS + row];
        tt[i] = FRESH ? 0 : si[SI_T + row];
        gr[i] = si[SI_GROW + row];
        long long bt = (long long)tt[i] * BSZ + gr[i];
        float u = (lane < NVOCAB) ? __ldg(&noise_tok[bt * NVOCAB + lane]) : 0.5f;
        g_t[i] = gumbelf(u);   // overlaps GEMV below
    }

    if (!FRESH) {
        // Phase A: z = W_hh * h ; lane owns j = lane + 32m ; k-quad vectorized
        u64 zp[CNT][4];
#pragma unroll
        for (int i = 0; i < CNT; i++)
#pragma unroll
            for (int m = 0; m < 4; m++) zp[i][m] = 0ull;
#pragma unroll 4
        for (int kq = 0; kq < 32; kq++) {
            u64 h01[CNT], h23[CNT];
#pragma unroll
            for (int i = 0; i < CNT; i++)
                lds2(h01[i], h23[i], sm + S_H + grp[i] * HIDN + 4 * kq);
#pragma unroll
            for (int m = 0; m < 4; m++) {
                u64 w01, w23;
                lds2(w01, w23, sm + S_WHH + (kq * 128 + lane + 32 * m) * 4);
#pragma unroll
                for (int i = 0; i < CNT; i++) {
                    zp[i][m] = ffma2(h01[i], w01, zp[i][m]);
                    zp[i][m] = ffma2(h23[i], w23, zp[i][m]);
                }
            }
        }
        float hnew[CNT][4];
#pragma unroll
        for (int i = 0; i < CNT; i++)
#pragma unroll
            for (int m = 0; m < 4; m++) {
                int j = lane + 32 * m;
                float z = f2lo(zp[i][m]) + f2hi(zp[i][m]);
                float a = sm[S_ACC + grp[i] * HIDN + j];
                hnew[i][m] = tanhf(z + a);
            }
        __syncwarp();
#pragma unroll
        for (int i = 0; i < CNT; i++)
#pragma unroll
            for (int m = 0; m < 4; m++)
                sm[S_H + grp[i] * HIDN + lane + 32 * m] = hnew[i][m];
        __syncwarp();
    }
    // (FRESH rows: refill already wrote h = tanh(acc) into S_H)

    // Phase B: token head logits (lane = vocab index), k-quad vectorized
    u64 tkp[CNT];
#pragma unroll
    for (int i = 0; i < CNT; i++) tkp[i] = 0ull;
#pragma unroll 4
    for (int kq = 0; kq < 32; kq++) {
        u64 w01, w23;
        lds2(w01, w23, sm + S_TOKP + (kq * 32 + lane) * 4);
#pragma unroll
        for (int i = 0; i < CNT; i++) {
            u64 h01, h23;
            lds2(h01, h23, sm + S_H + grp[i] * HIDN + 4 * kq);
            tkp[i] = ffma2(h01, w01, tkp[i]);
            tkp[i] = ffma2(h23, w23, tkp[i]);
        }
    }
    float btok = sm[S_BTOK + lane];
    const float NEGINF = -INFINITY;

    // Phase C1: batched softmax + Gumbel argmax across rows
    float ltok[CNT];
#pragma unroll
    for (int i = 0; i < CNT; i++) {
        float l = NEGINF;
        if (lane < NVOCAB) {
            l = f2lo(tkp[i]) + f2hi(tkp[i]) + btok;
            if (p[i] >= 15 && lane < 6) l = NEGINF;
        }
        ltok[i] = l;
    }
    float mx[CNT];
#pragma unroll
    for (int i = 0; i < CNT; i++) mx[i] = ltok[i];
#pragma unroll
    for (int o = 16; o; o >>= 1)
#pragma unroll
        for (int i = 0; i < CNT; i++)
            mx[i] = fmaxf(mx[i], __shfl_xor_sync(FULLM, mx[i], o));
    float sme[CNT];
#pragma unroll
    for (int i = 0; i < CNT; i++)
        sme[i] = (lane < NVOCAB) ? expf(ltok[i] - mx[i]) : 0.f;
#pragma unroll
    for (int o = 16; o; o >>= 1)
#pragma unroll
        for (int i = 0; i < CNT; i++)
            sme[i] += __shfl_xor_sync(FULLM, sme[i], o);
    float sc[CNT], lpw[CNT];
    int ci[CNT];
#pragma unroll
    for (int i = 0; i < CNT; i++) {
        float lse = logf(sme[i]);
        float lpt = ltok[i] - mx[i] - lse;
        sc[i]  = lpt + g_t[i];
        ci[i]  = lane;
        lpw[i] = lpt;
    }
#pragma unroll
    for (int o = 16; o; o >>= 1) {
#pragma unroll
        for (int i = 0; i < CNT; i++) {
            float s2 = __shfl_xor_sync(FULLM, sc[i], o);
            int   i2 = __shfl_xor_sync(FULLM, ci[i], o);
            float l2 = __shfl_xor_sync(FULLM, lpw[i], o);
            if (s2 > sc[i] || (s2 == sc[i] && i2 < ci[i])) {
                sc[i] = s2; ci[i] = i2; lpw[i] = l2;
            }
        }
    }

    // Phase C2: rare const head + bookkeeping
#pragma unroll
    for (int i = 0; i < CNT; i++) {
        int row = grp[i];
        int pi  = p[i];
        int choice = ci[i];
        float lp_tok = lpw[i];

        bool is_const = (choice == 18);
        float lp_c = 0.f; int cchoice = 0;
        if (is_const) {   // warp-uniform
            float2 co = make_float2(0.f, 0.f);
#pragma unroll 8
            for (int k4 = 0; k4 < 32; k4++) {
                float4 hv = *(const float4*)(sm + S_H + row * HIDN + 4 * k4);
#pragma unroll
                for (int b = 0; b < 4; b++) {
                    float2 wc = *(const float2*)(sm + S_CON + (4 * k4 + b) * 64 + 2 * lane);
                    float hk = (b == 0) ? hv.x : (b == 1) ? hv.y : (b == 2) ? hv.z : hv.w;
                    co.x = fmaf(hk, wc.x, co.x);
                    co.y = fmaf(hk, wc.y, co.y);
                }
            }
            long long bt = (long long)tt[i] * BSZ + gr[i];
            float2 uc = make_float2(0.f, 0.f);
            if (lane < 20) uc = *(const float2*)(&noise_c[bt * NCONST + 2 * lane]);
            float bc0 = sm[S_BCON + 2 * lane];
            float bc1 = sm[S_BCON + 2 * lane + 1];
            float la = (lane < 20) ? (co.x + bc0) : NEGINF;
            float lb = (lane < 20) ? (co.y + bc1) : NEGINF;
            float mc   = wmaxf(fmaxf(la, lb));
            float ec   = (lane < 20) ? (expf(la - mc) + expf(lb - mc)) : 0.f;
            float lsec = logf(wsumf(ec));
            float lpa = la - mc - lsec;
            float lpb = lb - mc - lsec;
            float sa = lpa + gumbelf(uc.x);
            float sb = lpb + gumbelf(uc.y);
            float s_l, lp_l; int i_l;
            if (sb > sa) { s_l = sb; i_l = 2 * lane + 1; lp_l = lpb; }
            else         { s_l = sa; i_l = 2 * lane;     lp_l = lpa; }
            wargmax(s_l, i_l, lp_l);
            cchoice = i_l; lp_c = lp_l;
        }

        if (lane == 0) {
            float lpn = (FRESH ? 0.f : sm[S_LP + row]) + lp_tok + (is_const ? lp_c : 0.f);
            out[gr[i] * TT + pi] = (float)choice;
            if (is_const) out[OUT_CV + gr[i] * TT + pi] = -10.f + 0.5f * (float)cchoice;
            int arity = (choice < 4) ? 2 : ((choice < 6) ? 1 : 0);
            int sp = FRESH ? 0 : si[SI_SP + row];
            if (arity == 2) {
                int wsp = sp < 7 ? sp : 7;
                si[SI_STK + row * 8 + wsp] = 2 * pi + 2;
            }
            int sp1 = sp + (arity == 2 ? 1 : 0);
            int nxt, sp2;
            if (arity != 0) { nxt = 2 * pi + 1; sp2 = sp1; }
            else {
                int ridx = sp1 - 1; if (ridx < 0) ridx = 0; if (ridx > 7) ridx = 7;
                nxt = (sp1 > 0) ? si[SI_STK + row * 8 + ridx] : -1;
                sp2 = (sp1 > 0) ? sp1 - 1 : 0;
            }
            if (nxt > TT - 1) nxt = -1;
            if (nxt >= 0) {
                sm[S_LP + row]   = lpn;
                si[SI_POS + row] = nxt;
                si[SI_SP + row]  = sp2;
                si[SI_T + row]   = tt[i] + 1;
            } else {
                si[SI_ACT + row] = 0;
                out[OUT_LP + gr[i]] = lpn;
            }
        }
        // fold chosen token code into W_ih accumulator
        if (choice & 15) {
            int cb = 4 * pi;
#pragma unroll
            for (int m = 0; m < 4; m++) {
                int j = lane + 32 * m;
                float a = sm[S_ACC + row * HIDN + j];
#pragma unroll
                for (int b = 0; b < 4; b++)
                    if (choice & (1 << b))
                        a += __ldg(&g_WihT[(cb + b) * HIDN + j]);
                sm[S_ACC + row * HIDN + j] = a;
            }
        }
    }
}

__device__ __forceinline__ void run_old(int cnt, float* sm, int* si,
        const float* nt, const float* nc, float* out, const int* grp, int lane)
{
    switch (cnt) {
        case 4: step_group<4, false>(sm, si, nt, nc, out, grp, lane); break;
        case 3: step_group<3, false>(sm, si, nt, nc, out, grp, lane); break;
        case 2: step_group<2, false>(sm, si, nt, nc, out, grp, lane); break;
        default: step_group<1, false>(sm, si, nt, nc, out, grp, lane); break;
    }
}
__device__ __forceinline__ void run_fresh(int cnt, float* sm, int* si,
        const float* nt, const float* nc, float* out, const int* grp, int lane)
{
    switch (cnt) {
        case 4: step_group<4, true>(sm, si, nt, nc, out, grp, lane); break;
        case 3: step_group<3, true>(sm, si, nt, nc, out, grp, lane); break;
        case 2: step_group<2, true>(sm, si, nt, nc, out, grp, lane); break;
        default: step_group<1, true>(sm, si, nt, nc, out, grp, lane); break;
    }
}

__global__ void __launch_bounds__(NTH, 1)
rnn_main(const float* __restrict__ x,
         const float* __restrict__ noise_tok,
         const float* __restrict__ noise_c,
         const float* __restrict__ W_ih,
         const float* __restrict__ W_hh,
         const float* __restrict__ b_ih,
         const float* __restrict__ b_hh,
         const float* __restrict__ W_out,
         const float* __restrict__ b_out,
         const float* __restrict__ W_c,
         const float* __restrict__ b_c,
         float* __restrict__ out)
{
    extern __shared__ float sm[];
    int* si = (int*)(sm + S_NF);
    int tid = threadIdx.x;
    int w = tid >> 5, lane = tid & 31;

    // ---- stage weights ----
    {   // W_hh k-quads: dst4[kq*128 + j] = {W_hh[j][4kq..4kq+3]}
        const float4* src = (const float4*)W_hh;   // [j][32]
        float4* dst = (float4*)(sm + S_WHH);
        for (int idx = tid; idx < 32 * 128; idx += NTH) {
            int kq = idx >> 7, j = idx & 127;
            dst[kq * 128 + j] = src[j * 32 + kq];
        }
    }
    {   // token head k-quads (zero-pad v 19..31)
        float4* dst = (float4*)(sm + S_TOKP);
        const float4 z4 = make_float4(0.f, 0.f, 0.f, 0.f);
        const float4* src = (const float4*)W_out;  // [v][32]
        for (int idx = tid; idx < 32 * 32; idx += NTH) {
            int kq = idx >> 5, v = idx & 31;
            dst[kq * 32 + v] = (v < NVOCAB) ? src[v * 32 + kq] : z4;
        }
    }
    for (int idx = tid; idx < HIDN * 64; idx += NTH) sm[S_CON + idx] = 0.f;
    __syncthreads();
    for (int idx = tid; idx < NCONST * HIDN; idx += NTH) {
        int c = idx / HIDN, k = idx % HIDN;
        sm[S_CON + k * 64 + c] = W_c[idx];
    }
    for (int idx = tid; idx < 9 * HIDN; idx += NTH) {
        int f = idx >> 7, j = idx & 127;
        sm[S_WX + f * 128 + j] = W_ih[j * INSZ + 124 + f];
    }
    if (tid < HIDN) sm[S_BSUM + tid] = b_ih[tid] + b_hh[tid];
    if (tid < 32) sm[S_BTOK + tid] = (tid < NVOCAB) ? b_out[tid] : 0.f;
    if (tid < 64) sm[S_BCON + tid] = (tid < NCONST) ? b_c[tid] : 0.f;
    if (tid < SLOTS) si[SI_ACT + tid] = 0;
    __syncthreads();

    // ---- persistent work loop ----
    for (;;) {
        if (w == 0) {
            int s0 = lane, s1 = 32 + lane;
            int f0 = si[SI_ACT + s0];
            int f1 = si[SI_ACT + s1];
            unsigned d0m = __ballot_sync(FULLM, !f0);
            unsigned d1m = __ballot_sync(FULLM, !f1);
            int nd0 = __popc(d0m);
            int nd = nd0 + __popc(d1m);
            int base = 0;
            if (lane == 0 && nd > 0) base = atomicAdd(&g_next, nd);
            base = __shfl_sync(FULLM, base, 0);
            int navail = BSZ - base;
            if (navail < 0) navail = 0;
            if (navail > nd) navail = nd;
            unsigned lt = (1u << lane) - 1u;
            int q0 = __popc(d0m & lt);
            int q1 = nd0 + __popc(d1m & lt);
            if (!f0) si[SI_DEAD + q0] = s0;
            if (!f1) si[SI_DEAD + q1] = s1;
            // survivors (old) first in LIST
            unsigned am0 = __ballot_sync(FULLM, f0 != 0);
            unsigned am1 = __ballot_sync(FULLM, f1 != 0);
            int c0 = __popc(am0);
            if (f0) si[SI_LIST + __popc(am0 & lt)] = s0;
            if (f1) si[SI_LIST + c0 + __popc(am1 & lt)] = s1;
            int oldc = c0 + __popc(am1);
            __syncwarp();
            // fresh appended after old
            for (int q = lane; q < navail; q += 32)
                si[SI_LIST + oldc + q] = si[SI_DEAD + q];
            if (lane == 0) {
                si[SI_CNT]     = oldc + navail;
                si[SI_CNT + 1] = navail;
                si[SI_CNT + 2] = base;
                si[SI_CNT + 3] = oldc;
            }
        }
        __syncthreads();
        int A = si[SI_CNT];
        int navail = si[SI_CNT + 1];
        int rbase  = si[SI_CNT + 2];
        int oldc   = si[SI_CNT + 3];
        if (A == 0) break;

        // refill: init acc and h = tanh(acc)  (first-step GEMV is identically zero)
        for (int q = w; q < navail; q += 16) {
            int slot = si[SI_DEAD + q];
            int gr = rbase + q;
            float xv[9];
#pragma unroll
            for (int f = 0; f < 9; f++) xv[f] = __ldg(&x[gr * 9 + f]);
#pragma unroll
            for (int m = 0; m < 4; m++) {
                int j = lane + 32 * m;
                float a = sm[S_BSUM + j];
#pragma unroll
                for (int f = 0; f < 9; f++) a = fmaf(xv[f], sm[S_WX + f * 128 + j], a);
                sm[S_ACC + slot * HIDN + j] = a;
                sm[S_H + slot * HIDN + j] = tanhf(a);
            }
            if (lane == 0) {
                si[SI_POS + slot]  = 0;
                si[SI_ACT + slot]  = 1;
                si[SI_GROW + slot] = gr;
            }
        }
        __syncthreads();

        int sbase = 4 * w;
        if (sbase < A) {
            int e  = sbase + 4 < A ? sbase + 4 : A;
            int oe = e < oldc ? e : oldc;
            int no = oe - sbase;                  // old rows for this warp
            if (no > 0) {
                int grp[4];
#pragma unroll
                for (int q = 0; q < 4; q++)
                    grp[q] = si[SI_LIST + sbase + (q < no ? q : 0)];
                run_old(no, sm, si, noise_tok, noise_c, out, grp, lane);
            }
            int fb = sbase > oldc ? sbase : oldc;
            int nf = e - fb;                      // fresh rows for this warp
            if (nf > 0) {
                int grp[4];
#pragma unroll
                for (int q = 0; q < 4; q++)
                    grp[q] = si[SI_LIST + fb + (q < nf ? q : 0)];
                run_fresh(nf, sm, si, noise_tok, noise_c, out, grp, lane);
            }
        }
        __syncthreads();
    }
}

// merged prep + output-init
__global__ void setup_kernel(const float* __restrict__ W_ih, float* __restrict__ out)
{
    int i = blockIdx.x * blockDim.x + threadIdx.x;
    if (i == 0) g_next = 0;
    if (i < INSZ * HIDN) {
        int c = i / HIDN, j = i % HIDN;
        g_WihT[c * HIDN + j] = W_ih[j * INSZ + c];
    }
    float4* o4 = (float4*)out;
    const int n4 = OUT_TOT / 4;
    int stride = gridDim.x * blockDim.x;
    for (int k = i; k < n4; k += stride) {
        float v = (k * 4 < OUT_CV) ? -1.f : 0.f;
        o4[k] = make_float4(v, v, v, v);
    }
}

extern "C" void kernel_launch(void* const* d_in, const int* in_sizes, int n_in,
                              void* d_out, int out_size)
{
    const float* x    = (const float*)d_in[0];
    const float* nt   = (const float*)d_in[1];
    const float* nc   = (const float*)d_in[2];
    const float* wih  = (const float*)d_in[3];
    const float* whh  = (const float*)d_in[4];
    const float* bih  = (const float*)d_in[5];
    const float* bhh  = (const float*)d_in[6];
    const float* wout = (const float*)d_in[7];
    const float* bout = (const float*)d_in[8];
    const float* wc   = (const float*)d_in[9];
    const float* bc   = (const float*)d_in[10];
    float* out = (float*)d_out;

    cudaFuncSetAttribute((const void*)rnn_main,
                         cudaFuncAttributeMaxDynamicSharedMemorySize, SMEM_BYTES);
    setup_kernel<<<512, 256>>>(wih, out);
    rnn_main<<<NBLK, NTH, SMEM_BYTES>>>(x, nt, nc, wih, whh, bih, bhh,
                                        wout, bout, wc, bc, out);
}